// round 3
// baseline (speedup 1.0000x reference)
#include <cuda_runtime.h>

#define NN 100000
#define DD 128
#define EE 600000

// ---------------- scratch (device globals: no runtime allocation) ----------------
__device__ float g_h[(size_t)NN * DD];
__device__ float g_m[(size_t)NN * DD];
__device__ float g_agg[(size_t)NN * DD];
__device__ float g_gi[(size_t)NN * 3 * DD];
__device__ float g_gh[(size_t)NN * 3 * DD];

// ---------------- packed f32x2 helpers ----------------
static __device__ __forceinline__ void ffma2(unsigned long long& d,
                                             unsigned long long a,
                                             unsigned long long b) {
    asm("fma.rn.f32x2 %0, %1, %2, %0;" : "+l"(d) : "l"(a), "l"(b));
}
static __device__ __forceinline__ unsigned long long bcast2(float v) {
    unsigned long long r;
    asm("mov.b64 %0, {%1, %1};" : "=l"(r) : "f"(v));
    return r;
}
static __device__ __forceinline__ void unpack2(unsigned long long p, float& lo, float& hi) {
    asm("mov.b64 {%0, %1}, %2;" : "=f"(lo), "=f"(hi) : "l"(p));
}

// ---------------- GEMM: C[N,M] = act( A[N,128] @ W[M,128]^T + bias ) ----------------
// BM=128, BN=128, BK=16, 256 threads, each thread 8x8 via f32x2 pairs along rows.
template <int ACTIN, int ACTOUT, bool BIAS>
__global__ __launch_bounds__(256, 2)
void gemm128(const float* __restrict__ A, const float* __restrict__ W,
             const float* __restrict__ bias, float* __restrict__ C, int M) {
    __shared__ __align__(16) float As[16][132];  // [k][row], pad 4 to dodge STS conflicts
    __shared__ __align__(16) float Bs[16][132];  // [k][m]

    const int tid = threadIdx.x;
    const int tx = tid & 15, ty = tid >> 4;
    const int n0 = blockIdx.x * 128;
    const int m0 = blockIdx.y * 128;

    unsigned long long acc[4][8];  // rows (2i,2i+1) packed, 8 cols
#pragma unroll
    for (int i = 0; i < 4; i++)
#pragma unroll
        for (int j = 0; j < 8; j++) acc[i][j] = 0ull;

    for (int k0 = 0; k0 < 128; k0 += 16) {
#pragma unroll
        for (int t = 0; t < 2; t++) {
            int f = tid + t * 256;      // float4 slot 0..511
            int row = f >> 2;           // 0..127
            int c4 = (f & 3) << 2;      // 0,4,8,12
            int gr = n0 + row;
            float4 v = make_float4(0.f, 0.f, 0.f, 0.f);
            if (gr < NN) v = *(const float4*)(A + (size_t)gr * 128 + k0 + c4);
            if (ACTIN == 1) {
                v.x = fmaxf(v.x, 0.f); v.y = fmaxf(v.y, 0.f);
                v.z = fmaxf(v.z, 0.f); v.w = fmaxf(v.w, 0.f);
            }
            As[c4 + 0][row] = v.x; As[c4 + 1][row] = v.y;
            As[c4 + 2][row] = v.z; As[c4 + 3][row] = v.w;
            float4 w = *(const float4*)(W + (size_t)(m0 + row) * 128 + k0 + c4);
            Bs[c4 + 0][row] = w.x; Bs[c4 + 1][row] = w.y;
            Bs[c4 + 2][row] = w.z; Bs[c4 + 3][row] = w.w;
        }
        __syncthreads();
#pragma unroll
        for (int kk = 0; kk < 16; kk++) {
            // a-pairs: adjacent rows -> direct 64-bit reinterpretation of LDS.128
            ulonglong2 pa01 = *(const ulonglong2*)(&As[kk][ty * 8]);
            ulonglong2 pa23 = *(const ulonglong2*)(&As[kk][ty * 8 + 4]);
            float4 b0 = *(const float4*)(&Bs[kk][tx * 8]);
            float4 b1 = *(const float4*)(&Bs[kk][tx * 8 + 4]);
            unsigned long long pa[4] = {pa01.x, pa01.y, pa23.x, pa23.y};
            unsigned long long pb[8] = {bcast2(b0.x), bcast2(b0.y), bcast2(b0.z), bcast2(b0.w),
                                        bcast2(b1.x), bcast2(b1.y), bcast2(b1.z), bcast2(b1.w)};
#pragma unroll
            for (int i = 0; i < 4; i++)
#pragma unroll
                for (int j = 0; j < 8; j++) ffma2(acc[i][j], pa[i], pb[j]);
        }
        __syncthreads();
    }

    // -------- epilogue --------
    float bv[8];
    if (BIAS) {
        float4 t0 = *(const float4*)(bias + m0 + tx * 8);
        float4 t1 = *(const float4*)(bias + m0 + tx * 8 + 4);
        bv[0] = t0.x; bv[1] = t0.y; bv[2] = t0.z; bv[3] = t0.w;
        bv[4] = t1.x; bv[5] = t1.y; bv[6] = t1.z; bv[7] = t1.w;
    } else {
#pragma unroll
        for (int j = 0; j < 8; j++) bv[j] = 0.f;
    }
    const int rbase = n0 + ty * 8;
#pragma unroll
    for (int i = 0; i < 4; i++) {
        float lo[8], hi[8];
#pragma unroll
        for (int j = 0; j < 8; j++) unpack2(acc[i][j], lo[j], hi[j]);
        int r0 = rbase + 2 * i, r1 = r0 + 1;
        if (r0 < NN) {
#pragma unroll
            for (int j = 0; j < 8; j++) {
                lo[j] += bv[j];
                if (ACTOUT == 1) lo[j] = fmaxf(lo[j], 0.f);
            }
            float* p = C + (size_t)r0 * M + m0 + tx * 8;
            *(float4*)p = make_float4(lo[0], lo[1], lo[2], lo[3]);
            *(float4*)(p + 4) = make_float4(lo[4], lo[5], lo[6], lo[7]);
        }
        if (r1 < NN) {
#pragma unroll
            for (int j = 0; j < 8; j++) {
                hi[j] += bv[j];
                if (ACTOUT == 1) hi[j] = fmaxf(hi[j], 0.f);
            }
            float* p = C + (size_t)r1 * M + m0 + tx * 8;
            *(float4*)p = make_float4(hi[0], hi[1], hi[2], hi[3]);
            *(float4*)(p + 4) = make_float4(hi[4], hi[5], hi[6], hi[7]);
        }
    }
}

// ---------------- zero agg ----------------
__global__ void zero_kernel(float4* __restrict__ p) {
    int i = blockIdx.x * blockDim.x + threadIdx.x;  // exactly NN*DD/4 threads
    p[i] = make_float4(0.f, 0.f, 0.f, 0.f);
}

// ---------------- scatter-add: agg[dst] += m[src], warp per edge ----------------
// Uses red.global.add.v4.f32 (sm_90+): one vector reduce per 16B, no return trip.
// Handles edge_index stored as int64 OR int32 (detected from data: int64 values
// must be < NN; int32 pair reinterpreted as int64 is >= 2^32 unless upper word 0).
__global__ void scatter_kernel(const float* __restrict__ m,
                               const void* __restrict__ ei_raw,
                               float* __restrict__ agg) {
    int t = blockIdx.x * blockDim.x + threadIdx.x;
    int e = t >> 5;
    int lane = t & 31;
    if (e >= EE) return;

    const long long* e64 = (const long long*)ei_raw;
    bool is64 = (((unsigned long long)e64[0] < (unsigned long long)NN) &&
                 ((unsigned long long)e64[1] < (unsigned long long)NN));
    int src, dst;
    if (is64) {
        src = (int)e64[e];
        dst = (int)e64[EE + e];
    } else {
        const int* e32 = (const int*)ei_raw;
        src = e32[e];
        dst = e32[EE + e];
    }
    float4 v = *(const float4*)(m + (size_t)src * DD + lane * 4);
    float* p = agg + (size_t)dst * DD + lane * 4;
    asm volatile("red.global.add.v4.f32 [%0], {%1, %2, %3, %4};"
                 :: "l"(p), "f"(v.x), "f"(v.y), "f"(v.z), "f"(v.w)
                 : "memory");
}

// ---------------- GRU gate fusion ----------------
static __device__ __forceinline__ float sigf(float x) { return 1.f / (1.f + __expf(-x)); }
static __device__ __forceinline__ float gate1(float ir, float iz, float in_,
                                              float hr, float hz, float hn, float hv) {
    float r = sigf(ir + hr);
    float z = sigf(iz + hz);
    float n = tanhf(in_ + r * hn);
    return (1.f - z) * n + z * hv;
}

__global__ void gru_gate(const float* __restrict__ gi, const float* __restrict__ gh,
                         float* __restrict__ h) {
    int t = blockIdx.x * blockDim.x + threadIdx.x;  // NN*32 threads, 4 dims each
    int n = t >> 5;
    int d4 = (t & 31) << 2;
    if (n >= NN) return;
    size_t bi = (size_t)n * 384 + d4;
    float4 ir = *(const float4*)(gi + bi);
    float4 iz = *(const float4*)(gi + bi + 128);
    float4 in_ = *(const float4*)(gi + bi + 256);
    float4 hr = *(const float4*)(gh + bi);
    float4 hz = *(const float4*)(gh + bi + 128);
    float4 hn = *(const float4*)(gh + bi + 256);
    float4* hp = (float4*)(h + (size_t)n * 128 + d4);
    float4 hv = *hp;
    float4 o;
    o.x = gate1(ir.x, iz.x, in_.x, hr.x, hz.x, hn.x, hv.x);
    o.y = gate1(ir.y, iz.y, in_.y, hr.y, hz.y, hn.y, hv.y);
    o.z = gate1(ir.z, iz.z, in_.z, hr.z, hz.z, hn.z, hv.z);
    o.w = gate1(ir.w, iz.w, in_.w, hr.w, hz.w, hn.w, hv.w);
    *hp = o;
}

// ---------------- launcher ----------------
extern "C" void kernel_launch(void* const* d_in, const int* in_sizes, int n_in,
                              void* d_out, int out_size) {
    const float* x     = (const float*)d_in[0];
    const void*  ei    = (const void*)d_in[1];   // int64 or int32, detected on device
    const float* W1    = (const float*)d_in[2];
    const float* b1    = (const float*)d_in[3];
    const float* Wconv = (const float*)d_in[4];
    const float* Wih   = (const float*)d_in[5];
    const float* Whh   = (const float*)d_in[6];
    const float* bih   = (const float*)d_in[7];
    const float* bhh   = (const float*)d_in[8];
    const float* W2    = (const float*)d_in[9];
    const float* b2    = (const float*)d_in[10];
    float* out = (float*)d_out;

    float *h, *m, *agg, *gi, *gh;
    cudaGetSymbolAddress((void**)&h, g_h);
    cudaGetSymbolAddress((void**)&m, g_m);
    cudaGetSymbolAddress((void**)&agg, g_agg);
    cudaGetSymbolAddress((void**)&gi, g_gi);
    cudaGetSymbolAddress((void**)&gh, g_gh);

    const int nb = (NN + 127) / 128;  // 782 row blocks
    dim3 blk(256);

    // h = relu(x @ W1^T + b1)
    gemm128<0, 1, true><<<dim3(nb, 1), blk>>>(x, W1, b1, h, DD);

    for (int l = 0; l < 3; l++) {
        // m = h @ Wconv[l]^T
        gemm128<0, 0, false><<<dim3(nb, 1), blk>>>(h, Wconv + (size_t)l * DD * DD, nullptr, m, DD);
        // agg = segment_sum(m[src], dst)
        zero_kernel<<<NN * DD / 4 / 256, 256>>>((float4*)agg);
        scatter_kernel<<<(EE * 32) / 256, 256>>>(m, ei, agg);
        // gi = agg @ Wih^T + bih ; gh = h @ Whh^T + bhh
        gemm128<0, 0, true><<<dim3(nb, 3), blk>>>(agg, Wih, bih, gi, 3 * DD);
        gemm128<0, 0, true><<<dim3(nb, 3), blk>>>(h, Whh, bhh, gh, 3 * DD);
        // h = GRU(agg, h)
        gru_gate<<<NN * 32 / 256, 256>>>(gi, gh, h);
    }

    // out = relu(h) @ W2^T + b2
    gemm128<1, 0, true><<<dim3(nb, 3), blk>>>(h, W2, b2, out, 3 * DD);
}

// round 5
// speedup vs baseline: 1.1987x; 1.1987x over previous
#include <cuda_runtime.h>
#include <cuda_bf16.h>
#include <cstdint>

#define NN 100000
#define DD 128
#define EE 600000
#define NTILES 782  // ceil(NN/128)

// ---------------- scratch (device globals: no runtime allocation) ----------------
__device__ float g_h[(size_t)NN * DD];
__device__ float g_m[(size_t)NN * DD];
__device__ float g_agg[(size_t)NN * DD];
__device__ float g_gi[(size_t)NN * 3 * DD];
__device__ float g_gh[(size_t)NN * 3 * DD];

// ---------------- helpers ----------------
static __device__ __forceinline__ uint32_t smem_u32(const void* p) {
    uint32_t a;
    asm("{ .reg .u64 t; cvta.to.shared.u64 t, %1; cvt.u32.u64 %0, t; }" : "=r"(a) : "l"(p));
    return a;
}

// ldmatrix x4 (four 8x8 b16 mats)
static __device__ __forceinline__ void ldsm4(uint32_t* r, uint32_t addr) {
    asm volatile("ldmatrix.sync.aligned.m8n8.x4.shared.b16 {%0,%1,%2,%3}, [%4];"
                 : "=r"(r[0]), "=r"(r[1]), "=r"(r[2]), "=r"(r[3]) : "r"(addr));
}

// bf16 mma m16n8k16, fp32 accumulate in place
static __device__ __forceinline__ void mma16816(float* d, const uint32_t* a, const uint32_t* b) {
    asm volatile(
        "mma.sync.aligned.m16n8k16.row.col.f32.bf16.bf16.f32 "
        "{%0,%1,%2,%3}, {%4,%5,%6,%7}, {%8,%9}, {%0,%1,%2,%3};"
        : "+f"(d[0]), "+f"(d[1]), "+f"(d[2]), "+f"(d[3])
        : "r"(a[0]), "r"(a[1]), "r"(a[2]), "r"(a[3]), "r"(b[0]), "r"(b[1]));
}

// swizzled byte offset within a 128x128 bf16 tile (rows of 256B; 16B chunks XOR'd by row)
static __device__ __forceinline__ uint32_t swz(uint32_t r, uint32_t c2) {
    return r * 256 + (c2 ^ ((r & 7) << 4));
}

// Dekker split of 4 floats into bf16 hi/lo packed words
static __device__ __forceinline__ void split4(float4 v, uint2& hi, uint2& lo) {
    __nv_bfloat16 h0 = __float2bfloat16(v.x), h1 = __float2bfloat16(v.y);
    __nv_bfloat16 h2 = __float2bfloat16(v.z), h3 = __float2bfloat16(v.w);
    __nv_bfloat16 l0 = __float2bfloat16(v.x - __bfloat162float(h0));
    __nv_bfloat16 l1 = __float2bfloat16(v.y - __bfloat162float(h1));
    __nv_bfloat16 l2 = __float2bfloat16(v.z - __bfloat162float(h2));
    __nv_bfloat16 l3 = __float2bfloat16(v.w - __bfloat162float(h3));
    hi.x = (uint32_t)__bfloat16_as_ushort(h0) | ((uint32_t)__bfloat16_as_ushort(h1) << 16);
    hi.y = (uint32_t)__bfloat16_as_ushort(h2) | ((uint32_t)__bfloat16_as_ushort(h3) << 16);
    lo.x = (uint32_t)__bfloat16_as_ushort(l0) | ((uint32_t)__bfloat16_as_ushort(l1) << 16);
    lo.y = (uint32_t)__bfloat16_as_ushort(l2) | ((uint32_t)__bfloat16_as_ushort(l3) << 16);
}

// SMEM layout: four 32KB bf16 tiles
#define SM_A_HI 0
#define SM_A_LO 32768
#define SM_B_HI 65536
#define SM_B_LO 98304
#define SM_TOTAL 131072

// ======== mma.sync GEMM: C[N, MT*128] = act( A[N,128] @ W[MT*128,128]^T + b ) ========
// 256 threads = 8 warps (2 row x 4 col); warp tile 64x32; 3-term bf16 split.
template <int ACTIN, int ACTOUT, int BIAS, int MT>
__global__ __launch_bounds__(256, 1)
void gemm_mma(const float* __restrict__ A, const float* __restrict__ W,
              const float* __restrict__ bias, float* __restrict__ C) {
    extern __shared__ char smem[];
    const uint32_t sb = smem_u32(smem);
    const int tid = threadIdx.x, lane = tid & 31, wid = tid >> 5;
    const int warp_m = (wid & 1) * 64;   // row offset in tile
    const int warp_n = (wid >> 1) * 32;  // col offset in tile
    const int n0 = blockIdx.x * 128;

    // ldmatrix lane-address components
    const int a_row = lane & 15;                              // A: rows 0-15
    const int a_kh = (lane >> 4) & 1;                         // A: k half
    const int b_row = (lane & 7) | (((lane >> 4) & 1) << 3);  // B: n rows
    const int b_kh = (lane >> 3) & 1;                         // B: k half

    // ---- fill + split A tile (128 rows x 128 k) ----
    for (int i = tid; i < 4096; i += 256) {
        int r = i >> 5, k = (i & 31) << 2;
        int gr = n0 + r;
        if (gr >= NN) gr = NN - 1;  // clamp; padded rows discarded at store
        float4 v = *(const float4*)(A + (size_t)gr * 128 + k);
        if (ACTIN) {
            v.x = fmaxf(v.x, 0.f); v.y = fmaxf(v.y, 0.f);
            v.z = fmaxf(v.z, 0.f); v.w = fmaxf(v.w, 0.f);
        }
        uint2 hi, lo;
        split4(v, hi, lo);
        uint32_t o = swz(r, k * 2);
        *(uint2*)(smem + SM_A_HI + o) = hi;
        *(uint2*)(smem + SM_A_LO + o) = lo;
    }

    for (int mt = 0; mt < MT; mt++) {
        // ---- fill + split W tile ----
        for (int i = tid; i < 4096; i += 256) {
            int r = i >> 5, k = (i & 31) << 2;
            float4 w = *(const float4*)(W + (size_t)(mt * 128 + r) * 128 + k);
            uint2 hi, lo;
            split4(w, hi, lo);
            uint32_t o = swz(r, k * 2);
            *(uint2*)(smem + SM_B_HI + o) = hi;
            *(uint2*)(smem + SM_B_LO + o) = lo;
        }
        __syncthreads();

        float acc[4][4][4];
#pragma unroll
        for (int t = 0; t < 4; t++)
#pragma unroll
            for (int u = 0; u < 4; u++)
#pragma unroll
                for (int q = 0; q < 4; q++) acc[t][u][q] = 0.f;

#pragma unroll 1
        for (int p = 0; p < 3; p++) {  // hi*hi, hi*lo, lo*hi
            const uint32_t Ab = sb + (p == 2 ? SM_A_LO : SM_A_HI);
            const uint32_t Bb = sb + (p == 1 ? SM_B_LO : SM_B_HI);
#pragma unroll
            for (int ks = 0; ks < 8; ks++) {
                const uint32_t c2a = ks * 32 + a_kh * 16;
                const uint32_t c2b = ks * 32 + b_kh * 16;
                uint32_t afr[4][4], bfr[4][2];
#pragma unroll
                for (int t = 0; t < 4; t++)
                    ldsm4(afr[t], Ab + swz(warp_m + t * 16 + a_row, c2a));
#pragma unroll
                for (int ub = 0; ub < 2; ub++) {
                    uint32_t tmp[4];
                    ldsm4(tmp, Bb + swz(warp_n + ub * 16 + b_row, c2b));
                    bfr[2 * ub][0] = tmp[0]; bfr[2 * ub][1] = tmp[1];
                    bfr[2 * ub + 1][0] = tmp[2]; bfr[2 * ub + 1][1] = tmp[3];
                }
#pragma unroll
                for (int t = 0; t < 4; t++)
#pragma unroll
                    for (int u = 0; u < 4; u++)
                        mma16816(acc[t][u], afr[t], bfr[u]);
            }
        }

        // ---- epilogue ----
        const int M = MT * 128;
        const int row0 = n0 + warp_m + (lane >> 2);
        const int colb = mt * 128 + warp_n + (lane & 3) * 2;
#pragma unroll
        for (int u = 0; u < 4; u++) {
            const int c = colb + u * 8;
            float b0 = 0.f, b1 = 0.f;
            if (BIAS) { b0 = __ldg(bias + c); b1 = __ldg(bias + c + 1); }
#pragma unroll
            for (int t = 0; t < 4; t++) {
                const int r = row0 + t * 16;
                float v0 = acc[t][u][0] + b0, v1 = acc[t][u][1] + b1;
                float v2 = acc[t][u][2] + b0, v3 = acc[t][u][3] + b1;
                if (ACTOUT) {
                    v0 = fmaxf(v0, 0.f); v1 = fmaxf(v1, 0.f);
                    v2 = fmaxf(v2, 0.f); v3 = fmaxf(v3, 0.f);
                }
                if (r < NN) *(float2*)(C + (size_t)r * M + c) = make_float2(v0, v1);
                if (r + 8 < NN) *(float2*)(C + (size_t)(r + 8) * M + c) = make_float2(v2, v3);
            }
        }
        __syncthreads();  // B consumed before next mt overwrites
    }
}

// ---------------- zero agg ----------------
__global__ void zero_kernel(float4* __restrict__ p) {
    int i = blockIdx.x * blockDim.x + threadIdx.x;
    p[i] = make_float4(0.f, 0.f, 0.f, 0.f);
}

// ---------------- scatter-add: agg[dst] += m[src], warp per edge (REDG v4) ----------------
__global__ void scatter_kernel(const float* __restrict__ m,
                               const void* __restrict__ ei_raw,
                               float* __restrict__ agg) {
    int t = blockIdx.x * blockDim.x + threadIdx.x;
    int e = t >> 5;
    int lane = t & 31;
    if (e >= EE) return;

    const long long* e64 = (const long long*)ei_raw;
    bool is64 = (((unsigned long long)e64[0] < (unsigned long long)NN) &&
                 ((unsigned long long)e64[1] < (unsigned long long)NN));
    int src, dst;
    if (is64) {
        src = (int)e64[e];
        dst = (int)e64[EE + e];
    } else {
        const int* e32 = (const int*)ei_raw;
        src = e32[e];
        dst = e32[EE + e];
    }
    float4 v = *(const float4*)(m + (size_t)src * DD + lane * 4);
    float* p = agg + (size_t)dst * DD + lane * 4;
    asm volatile("red.global.add.v4.f32 [%0], {%1, %2, %3, %4};"
                 :: "l"(p), "f"(v.x), "f"(v.y), "f"(v.z), "f"(v.w)
                 : "memory");
}

// ---------------- GRU gate fusion ----------------
static __device__ __forceinline__ float sigf(float x) { return 1.f / (1.f + __expf(-x)); }
static __device__ __forceinline__ float gate1(float ir, float iz, float in_,
                                              float hr, float hz, float hn, float hv) {
    float r = sigf(ir + hr);
    float z = sigf(iz + hz);
    float n = tanhf(in_ + r * hn);
    return (1.f - z) * n + z * hv;
}

__global__ void gru_gate(const float* __restrict__ gi, const float* __restrict__ gh,
                         float* __restrict__ h) {
    int t = blockIdx.x * blockDim.x + threadIdx.x;
    int n = t >> 5;
    int d4 = (t & 31) << 2;
    if (n >= NN) return;
    size_t bi = (size_t)n * 384 + d4;
    float4 ir = *(const float4*)(gi + bi);
    float4 iz = *(const float4*)(gi + bi + 128);
    float4 in_ = *(const float4*)(gi + bi + 256);
    float4 hr = *(const float4*)(gh + bi);
    float4 hz = *(const float4*)(gh + bi + 128);
    float4 hn = *(const float4*)(gh + bi + 256);
    float4* hp = (float4*)(h + (size_t)n * 128 + d4);
    float4 hv = *hp;
    float4 o;
    o.x = gate1(ir.x, iz.x, in_.x, hr.x, hz.x, hn.x, hv.x);
    o.y = gate1(ir.y, iz.y, in_.y, hr.y, hz.y, hn.y, hv.y);
    o.z = gate1(ir.z, iz.z, in_.z, hr.z, hz.z, hn.z, hv.z);
    o.w = gate1(ir.w, iz.w, in_.w, hr.w, hz.w, hn.w, hv.w);
    *hp = o;
}

// ---------------- launcher ----------------
extern "C" void kernel_launch(void* const* d_in, const int* in_sizes, int n_in,
                              void* d_out, int out_size) {
    const float* x     = (const float*)d_in[0];
    const void*  ei    = (const void*)d_in[1];
    const float* W1    = (const float*)d_in[2];
    const float* b1    = (const float*)d_in[3];
    const float* Wconv = (const float*)d_in[4];
    const float* Wih   = (const float*)d_in[5];
    const float* Whh   = (const float*)d_in[6];
    const float* bih   = (const float*)d_in[7];
    const float* bhh   = (const float*)d_in[8];
    const float* W2    = (const float*)d_in[9];
    const float* b2    = (const float*)d_in[10];
    float* out = (float*)d_out;

    float *h, *m, *agg, *gi, *gh;
    cudaGetSymbolAddress((void**)&h, g_h);
    cudaGetSymbolAddress((void**)&m, g_m);
    cudaGetSymbolAddress((void**)&agg, g_agg);
    cudaGetSymbolAddress((void**)&gi, g_gi);
    cudaGetSymbolAddress((void**)&gh, g_gh);

    cudaFuncSetAttribute(gemm_mma<0, 1, 1, 1>, cudaFuncAttributeMaxDynamicSharedMemorySize, SM_TOTAL);
    cudaFuncSetAttribute(gemm_mma<0, 0, 0, 1>, cudaFuncAttributeMaxDynamicSharedMemorySize, SM_TOTAL);
    cudaFuncSetAttribute(gemm_mma<0, 0, 1, 3>, cudaFuncAttributeMaxDynamicSharedMemorySize, SM_TOTAL);
    cudaFuncSetAttribute(gemm_mma<1, 0, 1, 3>, cudaFuncAttributeMaxDynamicSharedMemorySize, SM_TOTAL);

    // h = relu(x @ W1^T + b1)
    gemm_mma<0, 1, 1, 1><<<NTILES, 256, SM_TOTAL>>>(x, W1, b1, h);

    for (int l = 0; l < 3; l++) {
        // m = h @ Wconv[l]^T
        gemm_mma<0, 0, 0, 1><<<NTILES, 256, SM_TOTAL>>>(h, Wconv + (size_t)l * DD * DD, nullptr, m);
        // agg = segment_sum(m[src], dst)
        zero_kernel<<<NN * DD / 4 / 256, 256>>>((float4*)agg);
        scatter_kernel<<<(EE * 32) / 256, 256>>>(m, ei, agg);
        // gi = agg @ Wih^T + bih ; gh = h @ Whh^T + bhh
        gemm_mma<0, 0, 1, 3><<<NTILES, 256, SM_TOTAL>>>(agg, Wih, bih, gi);
        gemm_mma<0, 0, 1, 3><<<NTILES, 256, SM_TOTAL>>>(h, Whh, bhh, gh);
        // h = GRU(agg, h)
        gru_gate<<<NN * 32 / 256, 256>>>(gi, gh, h);
    }

    // out = relu(h) @ W2^T + b2
    gemm_mma<1, 0, 1, 3><<<NTILES, 256, SM_TOTAL>>>(h, W2, b2, out);
}

// round 6
// speedup vs baseline: 1.7448x; 1.4556x over previous
#include <cuda_runtime.h>
#include <cuda_bf16.h>
#include <cstdint>

#define NN 100000
#define DD 128
#define EE 600000
#define NT64 1563  // ceil(NN/64)

// ---------------- scratch (device globals: no runtime allocation) ----------------
__device__ float g_h[(size_t)NN * DD];
__device__ float g_m[(size_t)NN * DD];
__device__ float g_agg[(size_t)NN * DD];
__device__ float g_gi[(size_t)NN * 3 * DD];
__device__ float g_gh[(size_t)NN * 3 * DD];
// pre-split, pre-swizzled weights: 13 tiles of 128x128 bf16 (32KB blobs)
// order: W1 (tile 0), Wconv (1-3), Wih (4-6), Whh (7-9), W2 (10-12)
__device__ __nv_bfloat16 g_whi[13 * 16384];
__device__ __nv_bfloat16 g_wlo[13 * 16384];

// ---------------- helpers ----------------
static __device__ __forceinline__ uint32_t smem_u32(const void* p) {
    uint32_t a;
    asm("{ .reg .u64 t; cvta.to.shared.u64 t, %1; cvt.u32.u64 %0, t; }" : "=r"(a) : "l"(p));
    return a;
}
static __device__ __forceinline__ void ldsm4(uint32_t* r, uint32_t addr) {
    asm volatile("ldmatrix.sync.aligned.m8n8.x4.shared.b16 {%0,%1,%2,%3}, [%4];"
                 : "=r"(r[0]), "=r"(r[1]), "=r"(r[2]), "=r"(r[3]) : "r"(addr));
}
static __device__ __forceinline__ void mma16816(float* d, const uint32_t* a, const uint32_t* b) {
    asm volatile(
        "mma.sync.aligned.m16n8k16.row.col.f32.bf16.bf16.f32 "
        "{%0,%1,%2,%3}, {%4,%5,%6,%7}, {%8,%9}, {%0,%1,%2,%3};"
        : "+f"(d[0]), "+f"(d[1]), "+f"(d[2]), "+f"(d[3])
        : "r"(a[0]), "r"(a[1]), "r"(a[2]), "r"(a[3]), "r"(b[0]), "r"(b[1]));
}
static __device__ __forceinline__ void cpa16(uint32_t dst, const void* src) {
    asm volatile("cp.async.cg.shared.global [%0], [%1], 16;" :: "r"(dst), "l"(src) : "memory");
}
#define CP_COMMIT_WAIT() \
    asm volatile("cp.async.commit_group;\ncp.async.wait_group 0;" ::: "memory")

// swizzled byte offset within a tile (rows of 256B; 16B chunks XOR'd by row)
static __device__ __forceinline__ uint32_t swz(uint32_t r, uint32_t c2) {
    return r * 256 + (c2 ^ ((r & 7) << 4));
}

// Dekker split of 4 floats into bf16 hi/lo packed words
static __device__ __forceinline__ void split4(float4 v, uint2& hi, uint2& lo) {
    __nv_bfloat16 h0 = __float2bfloat16(v.x), h1 = __float2bfloat16(v.y);
    __nv_bfloat16 h2 = __float2bfloat16(v.z), h3 = __float2bfloat16(v.w);
    __nv_bfloat16 l0 = __float2bfloat16(v.x - __bfloat162float(h0));
    __nv_bfloat16 l1 = __float2bfloat16(v.y - __bfloat162float(h1));
    __nv_bfloat16 l2 = __float2bfloat16(v.z - __bfloat162float(h2));
    __nv_bfloat16 l3 = __float2bfloat16(v.w - __bfloat162float(h3));
    hi.x = (uint32_t)__bfloat16_as_ushort(h0) | ((uint32_t)__bfloat16_as_ushort(h1) << 16);
    hi.y = (uint32_t)__bfloat16_as_ushort(h2) | ((uint32_t)__bfloat16_as_ushort(h3) << 16);
    lo.x = (uint32_t)__bfloat16_as_ushort(l0) | ((uint32_t)__bfloat16_as_ushort(l1) << 16);
    lo.y = (uint32_t)__bfloat16_as_ushort(l2) | ((uint32_t)__bfloat16_as_ushort(l3) << 16);
}

// ---------------- weight prepass: split + swizzle all 13 tiles ----------------
__global__ void convert_w(const float* __restrict__ W1, const float* __restrict__ Wconv,
                          const float* __restrict__ Wih, const float* __restrict__ Whh,
                          const float* __restrict__ W2) {
    int i = blockIdx.x * blockDim.x + threadIdx.x;  // over 1664*128 elements
    if (i >= 1664 * 128) return;
    int row = i >> 7, k = i & 127;
    const float* src;
    int r;
    if (row < 128)       { src = W1;    r = row; }
    else if (row < 512)  { src = Wconv; r = row - 128; }
    else if (row < 896)  { src = Wih;   r = row - 512; }
    else if (row < 1280) { src = Whh;   r = row - 896; }
    else                 { src = W2;    r = row - 1280; }
    float v = src[(size_t)r * 128 + k];
    __nv_bfloat16 h = __float2bfloat16(v);
    __nv_bfloat16 l = __float2bfloat16(v - __bfloat162float(h));
    int tile = row >> 7, tr = row & 127;
    uint32_t o = swz((uint32_t)tr, (uint32_t)(2 * k));
    *(__nv_bfloat16*)((char*)g_whi + (size_t)tile * 32768 + o) = h;
    *(__nv_bfloat16*)((char*)g_wlo + (size_t)tile * 32768 + o) = l;
}

// SMEM: A hi/lo (64x128 = 16KB each), B hi/lo (128x128 = 32KB each) = 96KB
#define SM_A_HI 0
#define SM_A_LO 16384
#define SM_B_HI 32768
#define SM_B_LO 65536
#define SM_TOTAL 98304

// ======== mma.sync GEMM: C[N, MT*128] = act( A[N,128] @ W^T + b ) ========
// Tile 64(M) x 128(N); 8 warps = 2 row x 4 col, warp tile 32x32; 3-term bf16 split.
template <int ACTIN, int ACTOUT, int BIAS, int MT>
__global__ __launch_bounds__(256, 2)
void gemm_mma(const float* __restrict__ A, int wtile0,
              const float* __restrict__ bias, float* __restrict__ C) {
    extern __shared__ char smem[];
    const uint32_t sb = smem_u32(smem);
    const int tid = threadIdx.x, lane = tid & 31, wid = tid >> 5;
    const int warp_m = (wid & 1) * 32;
    const int warp_n = (wid >> 1) * 32;
    const int n0 = blockIdx.x * 64;

    const int a_row = lane & 15;
    const int a_kh = (lane >> 4) & 1;
    const int b_row = (lane & 7) | (((lane >> 4) & 1) << 3);
    const int b_kh = (lane >> 3) & 1;

    // ---- fill + split A tile (64 rows x 128 k), once per CTA ----
    for (int i = tid; i < 2048; i += 256) {
        int r = i >> 5, k = (i & 31) << 2;
        int gr = n0 + r;
        if (gr >= NN) gr = NN - 1;  // clamp; padded rows discarded at store
        float4 v = *(const float4*)(A + (size_t)gr * 128 + k);
        if (ACTIN) {
            v.x = fmaxf(v.x, 0.f); v.y = fmaxf(v.y, 0.f);
            v.z = fmaxf(v.z, 0.f); v.w = fmaxf(v.w, 0.f);
        }
        uint2 hi, lo;
        split4(v, hi, lo);
        uint32_t o = swz((uint32_t)r, (uint32_t)(k * 2));
        *(uint2*)(smem + SM_A_HI + o) = hi;
        *(uint2*)(smem + SM_A_LO + o) = lo;
    }

    for (int mt = 0; mt < MT; mt++) {
        // ---- W fill: identity cp.async copy of pre-swizzled blobs ----
        const char* whb = (const char*)g_whi + (size_t)(wtile0 + mt) * 32768;
        const char* wlb = (const char*)g_wlo + (size_t)(wtile0 + mt) * 32768;
        for (int i = tid; i < 2048; i += 256) {
            cpa16(sb + SM_B_HI + i * 16, whb + i * 16);
            cpa16(sb + SM_B_LO + i * 16, wlb + i * 16);
        }
        CP_COMMIT_WAIT();
        __syncthreads();

        float acc[2][4][4];
#pragma unroll
        for (int t = 0; t < 2; t++)
#pragma unroll
            for (int u = 0; u < 4; u++)
#pragma unroll
                for (int q = 0; q < 4; q++) acc[t][u][q] = 0.f;

#pragma unroll 1
        for (int p = 0; p < 3; p++) {  // hi*hi, hi*lo, lo*hi
            const uint32_t Ab = sb + (p == 2 ? SM_A_LO : SM_A_HI);
            const uint32_t Bb = sb + (p == 1 ? SM_B_LO : SM_B_HI);
#pragma unroll
            for (int ks = 0; ks < 8; ks++) {
                const uint32_t c2a = ks * 32 + a_kh * 16;
                const uint32_t c2b = ks * 32 + b_kh * 16;
                uint32_t afr[2][4], bfr[4][2];
#pragma unroll
                for (int t = 0; t < 2; t++)
                    ldsm4(afr[t], Ab + swz(warp_m + t * 16 + a_row, c2a));
#pragma unroll
                for (int ub = 0; ub < 2; ub++) {
                    uint32_t tmp[4];
                    ldsm4(tmp, Bb + swz(warp_n + ub * 16 + b_row, c2b));
                    bfr[2 * ub][0] = tmp[0]; bfr[2 * ub][1] = tmp[1];
                    bfr[2 * ub + 1][0] = tmp[2]; bfr[2 * ub + 1][1] = tmp[3];
                }
#pragma unroll
                for (int t = 0; t < 2; t++)
#pragma unroll
                    for (int u = 0; u < 4; u++)
                        mma16816(acc[t][u], afr[t], bfr[u]);
            }
        }

        // ---- epilogue ----
        const int M = MT * 128;
        const int row0 = n0 + warp_m + (lane >> 2);
        const int colb = mt * 128 + warp_n + (lane & 3) * 2;
#pragma unroll
        for (int u = 0; u < 4; u++) {
            const int c = colb + u * 8;
            float b0 = 0.f, b1 = 0.f;
            if (BIAS) { b0 = __ldg(bias + c); b1 = __ldg(bias + c + 1); }
#pragma unroll
            for (int t = 0; t < 2; t++) {
                const int r = row0 + t * 16;
                float v0 = acc[t][u][0] + b0, v1 = acc[t][u][1] + b1;
                float v2 = acc[t][u][2] + b0, v3 = acc[t][u][3] + b1;
                if (ACTOUT) {
                    v0 = fmaxf(v0, 0.f); v1 = fmaxf(v1, 0.f);
                    v2 = fmaxf(v2, 0.f); v3 = fmaxf(v3, 0.f);
                }
                if (r < NN) *(float2*)(C + (size_t)r * M + c) = make_float2(v0, v1);
                if (r + 8 < NN) *(float2*)(C + (size_t)(r + 8) * M + c) = make_float2(v2, v3);
            }
        }
        if (MT > 1) __syncthreads();  // B consumed before next mt overwrites
    }
}

// ---------------- zero agg ----------------
__global__ void zero_kernel(float4* __restrict__ p) {
    int i = blockIdx.x * blockDim.x + threadIdx.x;
    p[i] = make_float4(0.f, 0.f, 0.f, 0.f);
}

// ---------------- scatter-add: agg[dst] += m[src], warp per edge (REDG v4) ----------------
__global__ void scatter_kernel(const float* __restrict__ m,
                               const void* __restrict__ ei_raw,
                               float* __restrict__ agg) {
    int t = blockIdx.x * blockDim.x + threadIdx.x;
    int e = t >> 5;
    int lane = t & 31;
    if (e >= EE) return;

    const long long* e64 = (const long long*)ei_raw;
    bool is64 = (((unsigned long long)e64[0] < (unsigned long long)NN) &&
                 ((unsigned long long)e64[1] < (unsigned long long)NN));
    int src, dst;
    if (is64) {
        src = (int)e64[e];
        dst = (int)e64[EE + e];
    } else {
        const int* e32 = (const int*)ei_raw;
        src = e32[e];
        dst = e32[EE + e];
    }
    float4 v = *(const float4*)(m + (size_t)src * DD + lane * 4);
    float* p = agg + (size_t)dst * DD + lane * 4;
    asm volatile("red.global.add.v4.f32 [%0], {%1, %2, %3, %4};"
                 :: "l"(p), "f"(v.x), "f"(v.y), "f"(v.z), "f"(v.w)
                 : "memory");
}

// ---------------- GRU gate fusion ----------------
static __device__ __forceinline__ float sigf(float x) { return 1.f / (1.f + __expf(-x)); }
static __device__ __forceinline__ float gate1(float ir, float iz, float in_,
                                              float hr, float hz, float hn, float hv) {
    float r = sigf(ir + hr);
    float z = sigf(iz + hz);
    float n = tanhf(in_ + r * hn);
    return (1.f - z) * n + z * hv;
}

__global__ void gru_gate(const float* __restrict__ gi, const float* __restrict__ gh,
                         float* __restrict__ h) {
    int t = blockIdx.x * blockDim.x + threadIdx.x;
    int n = t >> 5;
    int d4 = (t & 31) << 2;
    if (n >= NN) return;
    size_t bi = (size_t)n * 384 + d4;
    float4 ir = *(const float4*)(gi + bi);
    float4 iz = *(const float4*)(gi + bi + 128);
    float4 in_ = *(const float4*)(gi + bi + 256);
    float4 hr = *(const float4*)(gh + bi);
    float4 hz = *(const float4*)(gh + bi + 128);
    float4 hn = *(const float4*)(gh + bi + 256);
    float4* hp = (float4*)(h + (size_t)n * 128 + d4);
    float4 hv = *hp;
    float4 o;
    o.x = gate1(ir.x, iz.x, in_.x, hr.x, hz.x, hn.x, hv.x);
    o.y = gate1(ir.y, iz.y, in_.y, hr.y, hz.y, hn.y, hv.y);
    o.z = gate1(ir.z, iz.z, in_.z, hr.z, hz.z, hn.z, hv.z);
    o.w = gate1(ir.w, iz.w, in_.w, hr.w, hz.w, hn.w, hv.w);
    *hp = o;
}

// ---------------- launcher ----------------
extern "C" void kernel_launch(void* const* d_in, const int* in_sizes, int n_in,
                              void* d_out, int out_size) {
    const float* x     = (const float*)d_in[0];
    const void*  ei    = (const void*)d_in[1];
    const float* W1    = (const float*)d_in[2];
    const float* b1    = (const float*)d_in[3];
    const float* Wconv = (const float*)d_in[4];
    const float* Wih   = (const float*)d_in[5];
    const float* Whh   = (const float*)d_in[6];
    const float* bih   = (const float*)d_in[7];
    const float* bhh   = (const float*)d_in[8];
    const float* W2    = (const float*)d_in[9];
    const float* b2    = (const float*)d_in[10];
    float* out = (float*)d_out;

    float *h, *m, *agg, *gi, *gh;
    cudaGetSymbolAddress((void**)&h, g_h);
    cudaGetSymbolAddress((void**)&m, g_m);
    cudaGetSymbolAddress((void**)&agg, g_agg);
    cudaGetSymbolAddress((void**)&gi, g_gi);
    cudaGetSymbolAddress((void**)&gh, g_gh);

    cudaFuncSetAttribute(gemm_mma<0, 1, 1, 1>, cudaFuncAttributeMaxDynamicSharedMemorySize, SM_TOTAL);
    cudaFuncSetAttribute(gemm_mma<0, 0, 0, 1>, cudaFuncAttributeMaxDynamicSharedMemorySize, SM_TOTAL);
    cudaFuncSetAttribute(gemm_mma<0, 0, 1, 3>, cudaFuncAttributeMaxDynamicSharedMemorySize, SM_TOTAL);
    cudaFuncSetAttribute(gemm_mma<1, 0, 1, 3>, cudaFuncAttributeMaxDynamicSharedMemorySize, SM_TOTAL);

    // prepass: split + swizzle all weights (tiles: W1=0, Wconv=1..3, Wih=4..6, Whh=7..9, W2=10..12)
    convert_w<<<(1664 * 128 + 255) / 256, 256>>>(W1, Wconv, Wih, Whh, W2);

    // h = relu(x @ W1^T + b1)
    gemm_mma<0, 1, 1, 1><<<NT64, 256, SM_TOTAL>>>(x, 0, b1, h);

    for (int l = 0; l < 3; l++) {
        // m = h @ Wconv[l]^T
        gemm_mma<0, 0, 0, 1><<<NT64, 256, SM_TOTAL>>>(h, 1 + l, nullptr, m);
        // agg = segment_sum(m[src], dst)
        zero_kernel<<<NN * DD / 4 / 256, 256>>>((float4*)agg);
        scatter_kernel<<<(EE * 32) / 256, 256>>>(m, ei, agg);
        // gi = agg @ Wih^T + bih ; gh = h @ Whh^T + bhh
        gemm_mma<0, 0, 1, 3><<<NT64, 256, SM_TOTAL>>>(agg, 4, bih, gi);
        gemm_mma<0, 0, 1, 3><<<NT64, 256, SM_TOTAL>>>(h, 7, bhh, gh);
        // h = GRU(agg, h)
        gru_gate<<<NN * 32 / 256, 256>>>(gi, gh, h);
    }

    // out = relu(h) @ W2^T + b2
    gemm_mma<1, 0, 1, 3><<<NT64, 256, SM_TOTAL>>>(h, 10, b2, out);
}

// round 7
// speedup vs baseline: 2.0154x; 1.1550x over previous
#include <cuda_runtime.h>
#include <cuda_bf16.h>
#include <cstdint>

#define NN 100000
#define DD 128
#define EE 600000
#define NT64 1563  // ceil(NN/64)

// ---------------- scratch (device globals: no runtime allocation) ----------------
__device__ float g_h[(size_t)NN * DD];
__device__ float g_agg[(size_t)NN * DD];     // scatter(h)
__device__ float g_gi[(size_t)NN * 3 * DD];
__device__ float g_gh[(size_t)NN * 3 * DD];
__device__ float g_wf[3 * 384 * 128];        // Wfused[l] = Wih @ Wconv[l]
// pre-split, pre-swizzled weights: 16 tiles of 128x128 bf16 (32KB blobs)
// tile order: W1 (0), Whh (1-3), W2 (4-6), Wfused (7-15)
__device__ __nv_bfloat16 g_whi[16 * 16384];
__device__ __nv_bfloat16 g_wlo[16 * 16384];

// ---------------- helpers ----------------
static __device__ __forceinline__ uint32_t smem_u32(const void* p) {
    uint32_t a;
    asm("{ .reg .u64 t; cvta.to.shared.u64 t, %1; cvt.u32.u64 %0, t; }" : "=r"(a) : "l"(p));
    return a;
}
static __device__ __forceinline__ void ldsm4(uint32_t* r, uint32_t addr) {
    asm volatile("ldmatrix.sync.aligned.m8n8.x4.shared.b16 {%0,%1,%2,%3}, [%4];"
                 : "=r"(r[0]), "=r"(r[1]), "=r"(r[2]), "=r"(r[3]) : "r"(addr));
}
static __device__ __forceinline__ void mma16816(float* d, const uint32_t* a, const uint32_t* b) {
    asm volatile(
        "mma.sync.aligned.m16n8k16.row.col.f32.bf16.bf16.f32 "
        "{%0,%1,%2,%3}, {%4,%5,%6,%7}, {%8,%9}, {%0,%1,%2,%3};"
        : "+f"(d[0]), "+f"(d[1]), "+f"(d[2]), "+f"(d[3])
        : "r"(a[0]), "r"(a[1]), "r"(a[2]), "r"(a[3]), "r"(b[0]), "r"(b[1]));
}
static __device__ __forceinline__ void cpa16(uint32_t dst, const void* src) {
    asm volatile("cp.async.cg.shared.global [%0], [%1], 16;" :: "r"(dst), "l"(src) : "memory");
}
#define CP_COMMIT_WAIT() \
    asm volatile("cp.async.commit_group;\ncp.async.wait_group 0;" ::: "memory")

// swizzled byte offset within a tile (rows of 256B; 16B chunks XOR'd by row)
static __device__ __forceinline__ uint32_t swz(uint32_t r, uint32_t c2) {
    return r * 256 + (c2 ^ ((r & 7) << 4));
}

// Dekker split of 4 floats into bf16 hi/lo packed words
static __device__ __forceinline__ void split4(float4 v, uint2& hi, uint2& lo) {
    __nv_bfloat16 h0 = __float2bfloat16(v.x), h1 = __float2bfloat16(v.y);
    __nv_bfloat16 h2 = __float2bfloat16(v.z), h3 = __float2bfloat16(v.w);
    __nv_bfloat16 l0 = __float2bfloat16(v.x - __bfloat162float(h0));
    __nv_bfloat16 l1 = __float2bfloat16(v.y - __bfloat162float(h1));
    __nv_bfloat16 l2 = __float2bfloat16(v.z - __bfloat162float(h2));
    __nv_bfloat16 l3 = __float2bfloat16(v.w - __bfloat162float(h3));
    hi.x = (uint32_t)__bfloat16_as_ushort(h0) | ((uint32_t)__bfloat16_as_ushort(h1) << 16);
    hi.y = (uint32_t)__bfloat16_as_ushort(h2) | ((uint32_t)__bfloat16_as_ushort(h3) << 16);
    lo.x = (uint32_t)__bfloat16_as_ushort(l0) | ((uint32_t)__bfloat16_as_ushort(l1) << 16);
    lo.y = (uint32_t)__bfloat16_as_ushort(l2) | ((uint32_t)__bfloat16_as_ushort(l3) << 16);
}

// ---------------- prepass 1: Wfused[l] = Wih @ Wconv[l]  (fp32) ----------------
__global__ void wfused_kernel(const float* __restrict__ Wih, const float* __restrict__ Wconv) {
    int i = blockIdx.x * blockDim.x + threadIdx.x;  // 3*384*128
    if (i >= 3 * 384 * 128) return;
    int l = i / (384 * 128), r = (i >> 7) % 384, k = i & 127;
    const float* wc = Wconv + (size_t)l * 128 * 128;
    float s = 0.f;
#pragma unroll 8
    for (int j = 0; j < 128; j++) s = fmaf(__ldg(Wih + r * 128 + j), __ldg(wc + j * 128 + k), s);
    g_wf[i] = s;
}

// ---------------- prepass 2: split + swizzle all 16 weight tiles ----------------
// rows: [0,128) W1; [128,512) Whh; [512,896) W2; [896,2048) Wfused
__global__ void convert_w(const float* __restrict__ W1, const float* __restrict__ Whh,
                          const float* __restrict__ W2) {
    int i = blockIdx.x * blockDim.x + threadIdx.x;  // 2048*128 elements
    if (i >= 2048 * 128) return;
    int row = i >> 7, k = i & 127;
    float v;
    if (row < 128)       v = W1[(size_t)row * 128 + k];
    else if (row < 512)  v = Whh[(size_t)(row - 128) * 128 + k];
    else if (row < 896)  v = W2[(size_t)(row - 512) * 128 + k];
    else                 v = g_wf[(size_t)(row - 896) * 128 + k];
    __nv_bfloat16 h = __float2bfloat16(v);
    __nv_bfloat16 l = __float2bfloat16(v - __bfloat162float(h));
    int tile = row >> 7, tr = row & 127;
    uint32_t o = swz((uint32_t)tr, (uint32_t)(2 * k));
    *(__nv_bfloat16*)((char*)g_whi + (size_t)tile * 32768 + o) = h;
    *(__nv_bfloat16*)((char*)g_wlo + (size_t)tile * 32768 + o) = l;
}

// SMEM: A hi/lo (64x128 = 16KB each), B hi/lo (128x128 = 32KB each) = 96KB
#define SM_A_HI 0
#define SM_A_LO 16384
#define SM_B_HI 32768
#define SM_B_LO 65536
#define SM_TOTAL 98304

// ======== mma.sync GEMM: C[N, MT*128] = act( A[N,128] @ W^T + b ) ========
// Tile 64(M) x 128(N); 8 warps = 2 row x 4 col, warp tile 32x32; 3-term bf16 split.
template <int ACTIN, int ACTOUT, int BIAS, int MT>
__global__ __launch_bounds__(256, 2)
void gemm_mma(const float* __restrict__ A, int wtile0,
              const float* __restrict__ bias, float* __restrict__ C) {
    extern __shared__ char smem[];
    const uint32_t sb = smem_u32(smem);
    const int tid = threadIdx.x, lane = tid & 31, wid = tid >> 5;
    const int warp_m = (wid & 1) * 32;
    const int warp_n = (wid >> 1) * 32;
    const int n0 = blockIdx.x * 64;

    const int a_row = lane & 15;
    const int a_kh = (lane >> 4) & 1;
    const int b_row = (lane & 7) | (((lane >> 4) & 1) << 3);
    const int b_kh = (lane >> 3) & 1;

    // ---- fill + split A tile (64 rows x 128 k), once per CTA ----
    for (int i = tid; i < 2048; i += 256) {
        int r = i >> 5, k = (i & 31) << 2;
        int gr = n0 + r;
        if (gr >= NN) gr = NN - 1;  // clamp; padded rows discarded at store
        float4 v = *(const float4*)(A + (size_t)gr * 128 + k);
        if (ACTIN) {
            v.x = fmaxf(v.x, 0.f); v.y = fmaxf(v.y, 0.f);
            v.z = fmaxf(v.z, 0.f); v.w = fmaxf(v.w, 0.f);
        }
        uint2 hi, lo;
        split4(v, hi, lo);
        uint32_t o = swz((uint32_t)r, (uint32_t)(k * 2));
        *(uint2*)(smem + SM_A_HI + o) = hi;
        *(uint2*)(smem + SM_A_LO + o) = lo;
    }

    for (int mt = 0; mt < MT; mt++) {
        // ---- W fill: identity cp.async copy of pre-swizzled blobs ----
        const char* whb = (const char*)g_whi + (size_t)(wtile0 + mt) * 32768;
        const char* wlb = (const char*)g_wlo + (size_t)(wtile0 + mt) * 32768;
        for (int i = tid; i < 2048; i += 256) {
            cpa16(sb + SM_B_HI + i * 16, whb + i * 16);
            cpa16(sb + SM_B_LO + i * 16, wlb + i * 16);
        }
        CP_COMMIT_WAIT();
        __syncthreads();

        float acc[2][4][4];
#pragma unroll
        for (int t = 0; t < 2; t++)
#pragma unroll
            for (int u = 0; u < 4; u++)
#pragma unroll
                for (int q = 0; q < 4; q++) acc[t][u][q] = 0.f;

#pragma unroll 1
        for (int p = 0; p < 3; p++) {  // hi*hi, hi*lo, lo*hi
            const uint32_t Ab = sb + (p == 2 ? SM_A_LO : SM_A_HI);
            const uint32_t Bb = sb + (p == 1 ? SM_B_LO : SM_B_HI);
#pragma unroll
            for (int ks = 0; ks < 8; ks++) {
                const uint32_t c2a = ks * 32 + a_kh * 16;
                const uint32_t c2b = ks * 32 + b_kh * 16;
                uint32_t afr[2][4], bfr[4][2];
#pragma unroll
                for (int t = 0; t < 2; t++)
                    ldsm4(afr[t], Ab + swz(warp_m + t * 16 + a_row, c2a));
#pragma unroll
                for (int ub = 0; ub < 2; ub++) {
                    uint32_t tmp[4];
                    ldsm4(tmp, Bb + swz(warp_n + ub * 16 + b_row, c2b));
                    bfr[2 * ub][0] = tmp[0]; bfr[2 * ub][1] = tmp[1];
                    bfr[2 * ub + 1][0] = tmp[2]; bfr[2 * ub + 1][1] = tmp[3];
                }
#pragma unroll
                for (int t = 0; t < 2; t++)
#pragma unroll
                    for (int u = 0; u < 4; u++)
                        mma16816(acc[t][u], afr[t], bfr[u]);
            }
        }

        // ---- epilogue ----
        const int M = MT * 128;
        const int row0 = n0 + warp_m + (lane >> 2);
        const int colb = mt * 128 + warp_n + (lane & 3) * 2;
#pragma unroll
        for (int u = 0; u < 4; u++) {
            const int c = colb + u * 8;
            float b0 = 0.f, b1 = 0.f;
            if (BIAS) { b0 = __ldg(bias + c); b1 = __ldg(bias + c + 1); }
#pragma unroll
            for (int t = 0; t < 2; t++) {
                const int r = row0 + t * 16;
                float v0 = acc[t][u][0] + b0, v1 = acc[t][u][1] + b1;
                float v2 = acc[t][u][2] + b0, v3 = acc[t][u][3] + b1;
                if (ACTOUT) {
                    v0 = fmaxf(v0, 0.f); v1 = fmaxf(v1, 0.f);
                    v2 = fmaxf(v2, 0.f); v3 = fmaxf(v3, 0.f);
                }
                if (r < NN) *(float2*)(C + (size_t)r * M + c) = make_float2(v0, v1);
                if (r + 8 < NN) *(float2*)(C + (size_t)(r + 8) * M + c) = make_float2(v2, v3);
            }
        }
        if (MT > 1) __syncthreads();  // B consumed before next mt overwrites
    }
}

// ---------------- zero agg ----------------
__global__ void zero_kernel(float4* __restrict__ p) {
    int i = blockIdx.x * blockDim.x + threadIdx.x;
    p[i] = make_float4(0.f, 0.f, 0.f, 0.f);
}

// ---------------- scatter-add: agg[dst] += h[src], warp per edge (REDG v4) ----------------
__global__ void scatter_kernel(const float* __restrict__ h,
                               const void* __restrict__ ei_raw,
                               float* __restrict__ agg) {
    int t = blockIdx.x * blockDim.x + threadIdx.x;
    int e = t >> 5;
    int lane = t & 31;
    if (e >= EE) return;

    const long long* e64 = (const long long*)ei_raw;
    bool is64 = (((unsigned long long)e64[0] < (unsigned long long)NN) &&
                 ((unsigned long long)e64[1] < (unsigned long long)NN));
    int src, dst;
    if (is64) {
        src = (int)e64[e];
        dst = (int)e64[EE + e];
    } else {
        const int* e32 = (const int*)ei_raw;
        src = e32[e];
        dst = e32[EE + e];
    }
    float4 v = *(const float4*)(h + (size_t)src * DD + lane * 4);
    float* p = agg + (size_t)dst * DD + lane * 4;
    asm volatile("red.global.add.v4.f32 [%0], {%1, %2, %3, %4};"
                 :: "l"(p), "f"(v.x), "f"(v.y), "f"(v.z), "f"(v.w)
                 : "memory");
}

// ---------------- GRU gate fusion ----------------
static __device__ __forceinline__ float sigf(float x) { return 1.f / (1.f + __expf(-x)); }
static __device__ __forceinline__ float gate1(float ir, float iz, float in_,
                                              float hr, float hz, float hn, float hv) {
    float r = sigf(ir + hr);
    float z = sigf(iz + hz);
    float n = tanhf(in_ + r * hn);
    return (1.f - z) * n + z * hv;
}

__global__ void gru_gate(const float* __restrict__ gi, const float* __restrict__ gh,
                         float* __restrict__ h) {
    int t = blockIdx.x * blockDim.x + threadIdx.x;
    int n = t >> 5;
    int d4 = (t & 31) << 2;
    if (n >= NN) return;
    size_t bi = (size_t)n * 384 + d4;
    float4 ir = *(const float4*)(gi + bi);
    float4 iz = *(const float4*)(gi + bi + 128);
    float4 in_ = *(const float4*)(gi + bi + 256);
    float4 hr = *(const float4*)(gh + bi);
    float4 hz = *(const float4*)(gh + bi + 128);
    float4 hn = *(const float4*)(gh + bi + 256);
    float4* hp = (float4*)(h + (size_t)n * 128 + d4);
    float4 hv = *hp;
    float4 o;
    o.x = gate1(ir.x, iz.x, in_.x, hr.x, hz.x, hn.x, hv.x);
    o.y = gate1(ir.y, iz.y, in_.y, hr.y, hz.y, hn.y, hv.y);
    o.z = gate1(ir.z, iz.z, in_.z, hr.z, hz.z, hn.z, hv.z);
    o.w = gate1(ir.w, iz.w, in_.w, hr.w, hz.w, hn.w, hv.w);
    *hp = o;
}

// ---------------- launcher ----------------
extern "C" void kernel_launch(void* const* d_in, const int* in_sizes, int n_in,
                              void* d_out, int out_size) {
    const float* x     = (const float*)d_in[0];
    const void*  ei    = (const void*)d_in[1];
    const float* W1    = (const float*)d_in[2];
    const float* b1    = (const float*)d_in[3];
    const float* Wconv = (const float*)d_in[4];
    const float* Wih   = (const float*)d_in[5];
    const float* Whh   = (const float*)d_in[6];
    const float* bih   = (const float*)d_in[7];
    const float* bhh   = (const float*)d_in[8];
    const float* W2    = (const float*)d_in[9];
    const float* b2    = (const float*)d_in[10];
    float* out = (float*)d_out;

    float *h, *agg, *gi, *gh;
    cudaGetSymbolAddress((void**)&h, g_h);
    cudaGetSymbolAddress((void**)&agg, g_agg);
    cudaGetSymbolAddress((void**)&gi, g_gi);
    cudaGetSymbolAddress((void**)&gh, g_gh);

    cudaFuncSetAttribute(gemm_mma<0, 1, 1, 1>, cudaFuncAttributeMaxDynamicSharedMemorySize, SM_TOTAL);
    cudaFuncSetAttribute(gemm_mma<0, 0, 1, 3>, cudaFuncAttributeMaxDynamicSharedMemorySize, SM_TOTAL);
    cudaFuncSetAttribute(gemm_mma<1, 0, 1, 3>, cudaFuncAttributeMaxDynamicSharedMemorySize, SM_TOTAL);

    // side stream + fork/join events (created and destroyed every call; capture-safe)
    cudaStream_t s2;
    cudaStreamCreateWithFlags(&s2, cudaStreamNonBlocking);
    cudaEvent_t evH[3], evG[3];
    for (int i = 0; i < 3; i++) {
        cudaEventCreateWithFlags(&evH[i], cudaEventDisableTiming);
        cudaEventCreateWithFlags(&evG[i], cudaEventDisableTiming);
    }

    // prepasses: Wfused then split+swizzle all 16 tiles
    wfused_kernel<<<(3 * 384 * 128 + 255) / 256, 256>>>(Wih, Wconv);
    convert_w<<<(2048 * 128 + 255) / 256, 256>>>(W1, Whh, W2);

    // h = relu(x @ W1^T + b1)
    gemm_mma<0, 1, 1, 1><<<NT64, 256, SM_TOTAL>>>(x, 0, b1, h);

    for (int l = 0; l < 3; l++) {
        // fork: gh = h @ Whh^T + bhh on s2, overlapping zero+scatter+gi on main
        cudaEventRecord(evH[l], 0);
        cudaStreamWaitEvent(s2, evH[l], 0);
        gemm_mma<0, 0, 1, 3><<<NT64, 256, SM_TOTAL, s2>>>(h, 1, bhh, gh);
        cudaEventRecord(evG[l], s2);

        // main: agg = scatter(h); gi = agg @ Wfused[l]^T + bih
        zero_kernel<<<NN * DD / 4 / 256, 256>>>((float4*)agg);
        scatter_kernel<<<(EE * 32) / 256, 256>>>(h, ei, agg);
        gemm_mma<0, 0, 1, 3><<<NT64, 256, SM_TOTAL>>>(agg, 7 + 3 * l, bih, gi);

        // join, then h = GRU(agg-path gi, gh)
        cudaStreamWaitEvent(0, evG[l], 0);
        gru_gate<<<NN * 32 / 256, 256>>>(gi, gh, h);
    }

    // out = relu(h) @ W2^T + b2
    gemm_mma<1, 0, 1, 3><<<NT64, 256, SM_TOTAL>>>(h, 4, b2, out);

    for (int i = 0; i < 3; i++) {
        cudaEventDestroy(evH[i]);
        cudaEventDestroy(evG[i]);
    }
    cudaStreamDestroy(s2);
}